// round 1
// baseline (speedup 1.0000x reference)
#include <cuda_runtime.h>
#include <cuda_bf16.h>

#define N_NODES 10000
#define D 128

// Scratch for aggregated messages h = segment_sum(x[src], dst). 5.12 MB.
__device__ float g_h[N_NODES * D];

// ---------------------------------------------------------------------------
// Kernel 1: zero h (must happen every launch — graph replays).
// ---------------------------------------------------------------------------
__global__ void zero_h_kernel() {
    int i = blockIdx.x * blockDim.x + threadIdx.x;
    if (i < N_NODES * D / 4) {
        ((float4*)g_h)[i] = make_float4(0.f, 0.f, 0.f, 0.f);
    }
}

// ---------------------------------------------------------------------------
// Kernel 2: edge scatter. One warp per edge: 32 lanes x float4 = 128 floats.
// Gather x[src] row (coalesced 512B) and vector-reduce into g_h[dst].
// ---------------------------------------------------------------------------
__global__ void scatter_kernel(const float* __restrict__ x,
                               const int* __restrict__ src,
                               const int* __restrict__ dst,
                               int n_edges) {
    int warp = (blockIdx.x * blockDim.x + threadIdx.x) >> 5;
    int lane = threadIdx.x & 31;
    if (warp >= n_edges) return;

    int s = src[warp];   // broadcast load (all lanes same addr)
    int d = dst[warp];

    const float4* xrow = (const float4*)(x + (long)s * D);
    float4 v = xrow[lane];

    float* p = g_h + (long)d * D + lane * 4;
    asm volatile("red.global.add.v4.f32 [%0], {%1,%2,%3,%4};"
                 :: "l"(p), "f"(v.x), "f"(v.y), "f"(v.z), "f"(v.w)
                 : "memory");
}

// ---------------------------------------------------------------------------
// Kernel 3: out = relu(h @ W + b).
// Block = 256 threads computes a 64(row) x 128(col) tile.
// Thread layout: tyc = tid&31 (col group, 4 cols each), tyr = tid>>5 (8 rows each).
// BK = 16. smem: h tile 4KB + W tile 8KB.
// ---------------------------------------------------------------------------
__global__ void gemm_bias_relu_kernel(const float* __restrict__ W,
                                      const float* __restrict__ b,
                                      float* __restrict__ out) {
    __shared__ float hs[64 * 16];
    __shared__ float ws[16 * 128];

    int row0 = blockIdx.x * 64;
    int tid  = threadIdx.x;
    int tyc  = tid & 31;   // 0..31 -> columns tyc*4 .. tyc*4+3
    int tyr  = tid >> 5;   // 0..7  -> rows tyr*8 .. tyr*8+7

    float acc[8][4];
#pragma unroll
    for (int i = 0; i < 8; i++)
#pragma unroll
        for (int j = 0; j < 4; j++) acc[i][j] = 0.f;

    for (int k0 = 0; k0 < D; k0 += 16) {
        // Load h tile: 64x16 = 1024 floats, 4 per thread.
        {
            int idx = tid * 4;
            int r   = idx >> 4;    // /16
            int kk  = idx & 15;
            int grow = row0 + r;
            float4 v = make_float4(0.f, 0.f, 0.f, 0.f);
            if (grow < N_NODES)
                v = *(const float4*)(g_h + grow * D + k0 + kk);
            *(float4*)&hs[idx] = v;
        }
        // Load W tile: 16x128 = 2048 floats, 8 per thread.
        {
            int idx = tid * 8;
            int kk  = idx >> 7;    // /128
            int c   = idx & 127;
            *(float4*)&ws[idx]     = *(const float4*)&W[(k0 + kk) * D + c];
            *(float4*)&ws[idx + 4] = *(const float4*)&W[(k0 + kk) * D + c + 4];
        }
        __syncthreads();

#pragma unroll
        for (int kk = 0; kk < 16; kk++) {
            float bb[4];
#pragma unroll
            for (int j = 0; j < 4; j++)
                bb[j] = ws[kk * 128 + tyc * 4 + j];   // conflict-free: lanes stride-1
#pragma unroll
            for (int i = 0; i < 8; i++) {
                float a = hs[(tyr * 8 + i) * 16 + kk]; // broadcast within warp
#pragma unroll
                for (int j = 0; j < 4; j++)
                    acc[i][j] = fmaf(a, bb[j], acc[i][j]);
            }
        }
        __syncthreads();
    }

#pragma unroll
    for (int i = 0; i < 8; i++) {
        int r = row0 + tyr * 8 + i;
        if (r < N_NODES) {
#pragma unroll
            for (int j = 0; j < 4; j++) {
                int c = tyc * 4 + j;
                out[r * D + c] = fmaxf(acc[i][j] + b[c], 0.f);
            }
        }
    }
}

// ---------------------------------------------------------------------------
// Launch: zero -> scatter -> gemm (default stream, graph-capturable).
// Inputs (metadata order): x [10000,128] f32, src [E] i32, dst [E] i32,
//                          W [128,128] f32, b [128] f32. Output: [10000,128] f32.
// ---------------------------------------------------------------------------
extern "C" void kernel_launch(void* const* d_in, const int* in_sizes, int n_in,
                              void* d_out, int out_size) {
    const float* x   = (const float*)d_in[0];
    const int*   src = (const int*)  d_in[1];
    const int*   dst = (const int*)  d_in[2];
    const float* W   = (const float*)d_in[3];
    const float* b   = (const float*)d_in[4];
    float*       out = (float*)d_out;
    int E = in_sizes[1];

    zero_h_kernel<<<(N_NODES * D / 4 + 255) / 256, 256>>>();

    const int warps_per_block = 8;
    int blocks = (E + warps_per_block - 1) / warps_per_block;
    scatter_kernel<<<blocks, warps_per_block * 32>>>(x, src, dst, E);

    gemm_bias_relu_kernel<<<(N_NODES + 63) / 64, 256>>>(W, b, out);
}